// round 8
// baseline (speedup 1.0000x reference)
#include <cuda_runtime.h>
#include <cstdint>

#define NROI 6144
#define NCLS 20
#define KSEL 615            // ceil(0.1 * 6144)
#define CSORT 1024
#define AW 20               // ceil(KSEL/32)
#define IOU_TH 0.25f
#define KPT 6               // keys per thread (6144/1024)
#define LMAX 16384
#define LCACHE 2048
#define NFINAL 48           // final-role blocks (128 ROIs each)

// ---- scratch (device globals; zero-initialized at load) ----
__device__ int g_list[LMAX];
__device__ unsigned long long g_lv[LMAX];    // packed (prob_bits<<32)|(NCLS-c)
__device__ int g_cnt;
__device__ volatile int g_done;              // class blocks finished
__device__ int g_done2;                      // final blocks finished

__device__ __forceinline__ void upd(float& mv, int& mj, float v, int j) {
    if (v > mv || (v == mv && j < mj)) { mv = v; mj = j; }
}

// ============================================================
// Single persistent kernel. Blocks 0..19: per-class NMS (publish
// compact kept list). Blocks 20..67: final gather/emit for a
// 128-ROI slab; they pre-zero their smem class table, spin on
// g_done, then gather with 8 chunks x 8-way ILP.
// ============================================================
__global__ void __launch_bounds__(1024, 1)
cim_kernel(const float* __restrict__ pc,
           const float* __restrict__ pd,
           const int* __restrict__ labels,
           const float* __restrict__ iou,
           float* __restrict__ out) {
    extern __shared__ unsigned long long dyn[];
    const int t = threadIdx.x;

    if (blockIdx.x < NCLS) {
        // ================= CLASS ROLE =================
        __shared__ unsigned long long cand[CSORT];
        __shared__ unsigned int sh_hist[256];
        __shared__ unsigned int sh_wsum[8];
        __shared__ unsigned int sh_prefix, sh_k;
        __shared__ int sh_nc, sh_next;
        __shared__ unsigned int am[AW];

        const int c = blockIdx.x;

        if (labels[c] == 0) {
            if (t == 0) { __threadfence(); atomicAdd((int*)&g_done, 1); }
            return;
        }

        // register-resident inverted keys
        unsigned int key[KPT];
        #pragma unroll
        for (int r = 0; r < KPT; ++r) {
            int i = t + r * 1024;
            float p = __ldg(&pc[i * (NCLS + 1) + c + 1]) *
                      __ldg(&pd[i * (NCLS + 1) + c + 1]);
            key[r] = ~__float_as_uint(p);
        }
        if (t == 0) { sh_prefix = 0; sh_k = KSEL; }
        __syncthreads();

        // ---- 4-pass MSB radix select ----
        for (int shift = 24; shift >= 0; shift -= 8) {
            if (t < 256) sh_hist[t] = 0;
            __syncthreads();
            const unsigned int prefix = sh_prefix;
            const unsigned int kcur   = sh_k;
            const unsigned int pmask  = (shift == 24) ? 0u : (0xFFFFFFFFu << (shift + 8));
            #pragma unroll
            for (int r = 0; r < KPT; ++r)
                if ((key[r] & pmask) == prefix)
                    atomicAdd(&sh_hist[(key[r] >> shift) & 0xFF], 1u);
            __syncthreads();
            unsigned int x = 0, hval = 0;
            if (t < 256) {
                hval = sh_hist[t];
                x = hval;
                #pragma unroll
                for (int off = 1; off < 32; off <<= 1) {
                    unsigned int y = __shfl_up_sync(0xFFFFFFFFu, x, off);
                    if ((t & 31) >= off) x += y;
                }
                if ((t & 31) == 31) sh_wsum[t >> 5] = x;
            }
            __syncthreads();
            if (t < 8) {
                unsigned int w = sh_wsum[t];
                #pragma unroll
                for (int off = 1; off < 8; off <<= 1) {
                    unsigned int y = __shfl_up_sync(0xFFu, w, off);
                    if (t >= off) w += y;
                }
                sh_wsum[t] = w;
            }
            __syncthreads();
            if (t < 256) {
                unsigned int incl = x + ((t >= 32) ? sh_wsum[(t >> 5) - 1] : 0u);
                unsigned int excl = incl - hval;
                if (incl >= kcur && excl < kcur) {
                    sh_prefix = prefix | ((unsigned int)t << shift);
                    sh_k = kcur - excl;
                }
            }
            __syncthreads();
        }
        const unsigned int thr = sh_prefix;

        // ---- compact ----
        if (t == 0) sh_nc = 0;
        __syncthreads();
        #pragma unroll
        for (int r = 0; r < KPT; ++r) {
            if (key[r] <= thr) {
                int pos = atomicAdd(&sh_nc, 1);
                if (pos < CSORT)
                    cand[pos] = ((unsigned long long)key[r] << 32) |
                                (unsigned int)(t + r * 1024);
            }
        }
        __syncthreads();
        const int nc = sh_nc;
        if (t >= nc && t < CSORT) cand[t] = 0xFFFFFFFFFFFFFFFFull;
        __syncthreads();

        // ---- bitonic sort 1024 u64 (shfl j<=16, smem j>=32) ----
        {
            unsigned long long v = cand[t];
            #pragma unroll
            for (unsigned int k = 2; k <= 32; k <<= 1) {
                bool asc = ((t & k) == 0);
                #pragma unroll
                for (unsigned int j = k >> 1; j >= 1; j >>= 1) {
                    unsigned long long o = __shfl_xor_sync(0xFFFFFFFFu, v, j);
                    bool keepmin = (((t & j) == 0) == asc);
                    v = (keepmin == (v <= o)) ? v : o;
                }
            }
            cand[t] = v;
        }
        __syncthreads();
        for (unsigned int k = 64; k <= CSORT; k <<= 1) {
            for (unsigned int j = k >> 1; j >= 32; j >>= 1) {
                unsigned int i = t, ixj = i ^ j;
                if (ixj > i) {
                    unsigned long long a = cand[i], b = cand[ixj];
                    bool asc = ((i & k) == 0);
                    if ((a > b) == asc) { cand[i] = b; cand[ixj] = a; }
                }
                __syncthreads();
            }
            {
                unsigned long long v = cand[t];
                bool asc = ((t & k) == 0);
                #pragma unroll
                for (unsigned int j = 16; j >= 1; j >>= 1) {
                    unsigned long long o = __shfl_xor_sync(0xFFFFFFFFu, v, j);
                    bool keepmin = (((t & j) == 0) == asc);
                    v = (keepmin == (v <= o)) ? v : o;
                }
                cand[t] = v;
            }
            __syncthreads();
        }

        // ---- greedy NMS; publish kept ----
        for (int w = t; w < AW; w += 1024) am[w] = 0xFFFFFFFFu;
        if (t == 0) {
            am[AW - 1] = (1u << (KSEL - 32 * (AW - 1))) - 1;
            sh_next = 0;
        }
        __syncthreads();

        while (true) {
            const int i = sh_next;
            if (i >= KSEL) break;
            const unsigned long long ci = cand[i];
            const int oi = (unsigned int)ci;
            if (t == 0) {
                unsigned int pbits = ~(unsigned int)(ci >> 32);
                int pos = atomicAdd(&g_cnt, 1);
                g_list[pos] = oi;
                g_lv[pos] = ((unsigned long long)pbits << 32) |
                            (unsigned long long)(unsigned int)(NCLS - c);
            }
            const int j = i + 1 + t;
            if (j < KSEL) {
                const int oj = (unsigned int)cand[j];
                float v = iou[(size_t)oi * NROI + oj];
                if (v >= IOU_TH) atomicAnd(&am[j >> 5], ~(1u << (j & 31)));
            }
            __syncthreads();
            if (t == 0) {
                int nx = KSEL;
                int start = i + 1;
                int w = start >> 5;
                unsigned int m = (w < AW) ? (am[w] & (0xFFFFFFFFu << (start & 31))) : 0u;
                while (true) {
                    if (m) { nx = (w << 5) + __ffs(m) - 1; break; }
                    if (++w >= AW) break;
                    m = am[w];
                }
                sh_next = nx;
            }
            __syncthreads();
        }
        if (t == 0) { __threadfence(); atomicAdd((int*)&g_done, 1); }
        return;
    }

    // ================= FINAL ROLE =================
    unsigned long long* s_cw   = dyn;                   // NROI u64 = 48KB
    unsigned long long* s_part = dyn + NROI;            // 1024 u64 = 8KB
    int*   s_list = (int*)(s_part + 1024);              // LCACHE ints = 8KB
    int*   s_lab  = s_list + LCACHE;                    // 128
    float* s_v    = (float*)(s_lab + 128);              // 128
    float* s_w    = s_v + 128;                          // 128

    const int bi = blockIdx.x - NCLS;                   // 0..NFINAL-1
    const int il = t & 127;
    const int ch = t >> 7;                              // 0..7
    const int i  = bi * 128 + il;

    // overlap: zero class table while class blocks run
    for (int e = t; e < NROI; e += 1024) s_cw[e] = 0ull;
    __syncthreads();

    // wait for all class blocks
    if (t == 0) {
        while (g_done < NCLS) __nanosleep(64);
    }
    __syncthreads();
    __threadfence();

    const int G = g_cnt;

    // build class table + cache list in smem
    for (int e = t; e < G; e += 1024) {
        int oi = g_list[e];
        if (e < LCACHE) s_list[e] = oi;
        atomicMax(&s_cw[oi], g_lv[e]);
    }
    __syncthreads();

    // gather: chunk ch of [0,G), 8-way ILP
    const int len = (G + 7) >> 3;
    const int g0 = ch * len;
    const int g1 = min(G, g0 + len);

    unsigned long long pkey = 0ull;
    if (g0 < g1) {
        float mv[8]; int mj[8];
        #pragma unroll
        for (int r = 0; r < 8; ++r) { mv[r] = -1.0f; mj[r] = 0; }
        if (g1 <= LCACHE) {
            int g = g0;
            for (; g + 8 <= g1; g += 8) {
                #pragma unroll
                for (int r = 0; r < 8; ++r) {
                    int j = s_list[g + r];
                    upd(mv[r], mj[r], iou[(size_t)j * NROI + i], j);
                }
            }
            for (; g < g1; ++g) {
                int j = s_list[g];
                upd(mv[0], mj[0], iou[(size_t)j * NROI + i], j);
            }
        } else {
            int g = g0;
            for (; g + 8 <= g1; g += 8) {
                #pragma unroll
                for (int r = 0; r < 8; ++r) {
                    int j = __ldg(&g_list[g + r]);
                    upd(mv[r], mj[r], iou[(size_t)j * NROI + i], j);
                }
            }
            for (; g < g1; ++g) {
                int j = __ldg(&g_list[g]);
                upd(mv[0], mj[0], iou[(size_t)j * NROI + i], j);
            }
        }
        #pragma unroll
        for (int r = 4; r >= 1; r >>= 1)
            #pragma unroll
            for (int r2 = 0; r2 < 8; ++r2)
                if (r2 < r) upd(mv[r2], mj[r2], mv[r2 + r], mj[r2 + r]);
        pkey = ((unsigned long long)__float_as_uint(mv[0]) << 32) |
               (unsigned long long)(unsigned int)(NROI - mj[0]);
    }
    s_part[t] = pkey;
    __syncthreads();

    // reduce 8 chunks + class lookup + staging (threads 0..127)
    if (t < 128) {
        unsigned long long best = s_part[t];
        #pragma unroll
        for (int r = 1; r < 8; ++r) {
            unsigned long long b2 = s_part[t + r * 128];
            if (b2 > best) best = b2;
        }
        const float maxv = __uint_as_float((unsigned int)(best >> 32));
        const int   maxj = NROI - (int)(unsigned int)(best & 0xFFFFFFFFull);

        const unsigned long long cw = s_cw[maxj];
        const int   cls = (int)(NCLS + 1) - (int)(unsigned int)(cw & 0xFFFFFFFFull);
        const float lw  = __uint_as_float((unsigned int)(cw >> 32));

        const bool ignore = (maxv == 0.0f);
        const bool bg     = (maxv < IOU_TH) && !ignore;
        s_lab[t] = ignore ? -1 : (bg ? 0 : cls);
        s_v[t]   = maxv;
        s_w[t]   = ignore ? 0.0f : lw;
    }
    __syncthreads();

    // coalesced emit: 128 rows x 21 one-hot
    const size_t base = (size_t)bi * 128 * (NCLS + 1);
    for (int e = t; e < 128 * (NCLS + 1); e += 1024) {
        int row = e / (NCLS + 1);
        int k   = e - row * (NCLS + 1);
        out[base + e] = (k == s_lab[row]) ? 1.0f : 0.0f;
    }
    if (t < 128) {
        out[(size_t)NROI * (NCLS + 1) + i]        = s_v[t];
        out[(size_t)NROI * (NCLS + 1) + NROI + i] = s_w[t];
    }

    // last final block resets state for the next graph replay
    __syncthreads();
    if (t == 0) {
        __threadfence();
        int old = atomicAdd(&g_done2, 1);
        if (old == NFINAL - 1) {
            g_cnt = 0;
            g_done2 = 0;
            __threadfence();
            g_done = 0;
        }
    }
}

extern "C" void kernel_launch(void* const* d_in, const int* in_sizes, int n_in,
                              void* d_out, int out_size) {
    const float* pc     = (const float*)d_in[0];
    const float* pd     = (const float*)d_in[1];
    // d_in[2] = rois (unused)
    const int*   labels = (const int*)d_in[3];
    const float* iou    = (const float*)d_in[4];
    float* out = (float*)d_out;

    const int dsmem = NROI * 8 + 1024 * 8 + LCACHE * 4 + 128 * 12;
    cudaFuncSetAttribute(cim_kernel,
                         cudaFuncAttributeMaxDynamicSharedMemorySize, dsmem);

    cim_kernel<<<NCLS + NFINAL, 1024, dsmem>>>(pc, pd, labels, iou, out);
}